// round 6
// baseline (speedup 1.0000x reference)
#include <cuda_runtime.h>
#include <math.h>

#define IMG    256
#define TS     32     // output tile
#define PSZ    16
#define PAD    8
#define CH     3
#define NBR    64
#define INV2S2 12.5f
#define EPSV   1e-7f
#define PACC   36     // acc row pitch (floats)
#define PADP   20     // patchT row pitch [c][q][p]
#define PF     28     // FxT/FyT row pitch
#define PT     28     // tT row pitch

__global__ __launch_bounds__(256) void brush_tile_kernel(
    const float* __restrict__ brushes,   // [B, N, 2]
    const float* __restrict__ patches,   // [B, N, 3, 16, 16]
    float* __restrict__ out)             // [B, 3, 256, 256]
{
    __shared__ __align__(16) float acc_s[CH][TS][PACC];
    __shared__ __align__(16) float patchT_s[CH * PSZ * PADP];
    __shared__ __align__(16) float FxT_s[PSZ * PF];
    __shared__ __align__(16) float FyT_s[PSZ * PF];
    __shared__ __align__(16) float tT_s[CH * PSZ * PT];
    __shared__ float gx_s[NBR], gy_s[NBR];
    __shared__ float e_s[2][8];
    __shared__ float rden_s[2][16];

    const int tid  = threadIdx.x;
    const int b    = blockIdx.x >> 6;
    const int tile = blockIdx.x & 63;
    const int h0t  = (tile >> 3) * TS;
    const int w0t  = (tile & 7) * TS;

    // zero accumulators (incl. padding)
    {
        float4* a4 = (float4*)&acc_s[0][0][0];
        #pragma unroll
        for (int k = 0; k < 4; k++) {
            const int i = tid + k * 256;
            if (i < CH * TS * PACC / 4) a4[i] = make_float4(0.f, 0.f, 0.f, 0.f);
        }
    }
    // stage brush coords (scaled)
    if (tid < NBR) {
        gx_s[tid] = brushes[((size_t)b * NBR + tid) * 2 + 0] * (float)IMG;
        gy_s[tid] = brushes[((size_t)b * NBR + tid) * 2 + 1] * (float)IMG;
    }
    __syncthreads();

    for (int n = 0; n < NBR; n++) {
        const float gx = gx_s[n], gy = gy_s[n];
        const int t0x = (int)floorf(gx) - 10;
        const int t0y = (int)floorf(gy) - 10;
        const int bx0 = t0x - w0t;            // brush support: [bx0, bx0+23)
        const int by0 = t0y - h0t;
        if (bx0 >= TS || bx0 + 23 <= 0 || by0 >= TS || by0 + 23 <= 0) continue;

        const int wa0 = max(bx0, 0) & ~3;
        const int ha0 = max(by0, 0) & ~3;
        const int nwq = (min(bx0 + 23, TS) - wa0 + 3) >> 2;   // <= 7
        const int nhq = (min(by0 + 23, TS) - ha0 + 3) >> 2;   // <= 7

        // ---- phase A: exp tables (warp 0) + patch transpose load (threads 64+) ----
        if (tid < 32) {
            if (tid < 16) {
                const int ax = tid >> 3, k = tid & 7;
                const float g = ax ? gy : gx;
                const int t0 = ax ? t0y : t0x;
                const float d = (float)(t0 + k) - (g - 7.5f);
                e_s[ax][k] = __expf(-d * d * INV2S2);
            }
            __syncwarp();
            {
                const int ax = tid >> 4, q = tid & 15;
                const int t0 = ax ? t0y : t0x;
                int klo = -PAD - q - t0;            if (klo < 0) klo = 0;
                int khi = (IMG + PAD - 1) - q - t0; if (khi > 7) khi = 7;
                float s = 0.f;
                #pragma unroll
                for (int kk = 0; kk < 8; kk++)
                    if (kk >= klo && kk <= khi) s += e_s[ax][kk];
                s += EPSV;
                rden_s[ax][q] = (ax == 0) ? 1.f / (s * (float)NBR) : 1.f / s;
            }
        } else if (tid >= 64) {
            const float* pbase = patches + ((size_t)b * NBR + n) * (CH * PSZ * PSZ);
            const int t = tid - 64;
            #pragma unroll
            for (int it = 0; it < 4; it++) {
                const int i = t + it * 192;
                const int c = i >> 8, r = i & 255, p = r >> 4, q = r & 15;
                patchT_s[(c * PSZ + q) * PADP + p] = pbase[i];
            }
        }
        __syncthreads();

        // ---- phase B: fill FxT[q][wl], FyT[p][hl] (full 16x28 each; fringe=0) ----
        for (int i = tid; i < 2 * PSZ * PF; i += 256) {
            const int ax = i >= PSZ * PF;
            const int r  = i - ax * (PSZ * PF);
            const int q  = r / PF;
            const int l  = r - q * PF;
            if (ax == 0) {
                const int w   = w0t + wa0 + l;
                const int idx = w - q - t0x;
                FxT_s[r] = ((unsigned)idx < 8u) ? e_s[0][idx] * rden_s[0][q] : 0.f;
            } else {
                const int h   = h0t + ha0 + l;
                const int idx = h - q - t0y;
                FyT_s[r] = ((unsigned)idx < 8u) ? e_s[1][idx] * rden_s[1][q] : 0.f;
            }
        }
        __syncthreads();

        // ---- stage 1: tT[c][p][wl] = sum_q FxT[q][wl] * patchT[c][q][p] ----
        const int s1tasks = CH * 4 * nwq;   // <= 84
        if (tid < s1tasks) {
            const int wlq = tid % nwq;
            int u = tid / nwq;
            const int pg = u & 3;
            const int c  = u >> 2;
            const int p0  = pg * 4;
            const int wl0 = wlq * 4;

            float acc[4][4] = {};   // [wl][p]
            #pragma unroll
            for (int q = 0; q < PSZ; q++) {
                const float4 fx = *(const float4*)&FxT_s[q * PF + wl0];
                const float4 pv = *(const float4*)&patchT_s[(c * PSZ + q) * PADP + p0];
                const float fxa[4] = {fx.x, fx.y, fx.z, fx.w};
                const float pva[4] = {pv.x, pv.y, pv.z, pv.w};
                #pragma unroll
                for (int i = 0; i < 4; i++)
                    #pragma unroll
                    for (int pp = 0; pp < 4; pp++)
                        acc[i][pp] = fmaf(fxa[i], pva[pp], acc[i][pp]);
            }
            #pragma unroll
            for (int pp = 0; pp < 4; pp++) {
                float4 o = make_float4(acc[0][pp], acc[1][pp], acc[2][pp], acc[3][pp]);
                *(float4*)&tT_s[(c * PSZ + p0 + pp) * PT + wl0] = o;
            }
        }
        __syncthreads();

        // ---- stage 2: acc[c][ha0+hl][wa0+wl] += sum_p tT[c][p][wl] * FyT[p][hl] ----
        const int s2tasks = CH * nhq * nwq;   // <= 147
        if (tid < s2tasks) {
            const int wq = tid % nwq;
            int u = tid / nwq;
            const int hq = u % nhq;
            const int c  = u / nhq;
            const int wl0 = wq * 4;
            const int hl0 = hq * 4;

            float acc[4][4] = {};   // [hl][wl]
            #pragma unroll
            for (int p = 0; p < PSZ; p++) {
                const float4 tv = *(const float4*)&tT_s[(c * PSZ + p) * PT + wl0];
                const float4 fy = *(const float4*)&FyT_s[p * PF + hl0];
                const float fya[4] = {fy.x, fy.y, fy.z, fy.w};
                const float tva[4] = {tv.x, tv.y, tv.z, tv.w};
                #pragma unroll
                for (int i = 0; i < 4; i++)
                    #pragma unroll
                    for (int k = 0; k < 4; k++)
                        acc[i][k] = fmaf(fya[i], tva[k], acc[i][k]);
            }
            #pragma unroll
            for (int i = 0; i < 4; i++) {
                float4* dst = (float4*)&acc_s[c][ha0 + hl0 + i][wa0 + wl0];
                float4 v = *dst;
                v.x += acc[i][0]; v.y += acc[i][1];
                v.z += acc[i][2]; v.w += acc[i][3];
                *dst = v;
            }
        }
        __syncthreads();
    }

    // ---- final: write tile to gmem (coalesced STG.128) ----
    #pragma unroll
    for (int k = 0; k < 3; k++) {
        const int t  = tid + k * 256;       // 768 float4 tasks
        const int c  = t >> 8;
        const int r  = t & 255;
        const int hl = r >> 3;
        const int wq = r & 7;
        const float4 v = *(const float4*)&acc_s[c][hl][wq * 4];
        float* dst = out + (((size_t)b * CH + c) * IMG + (h0t + hl)) * IMG + w0t + wq * 4;
        *(float4*)dst = v;
    }
}

extern "C" void kernel_launch(void* const* d_in, const int* in_sizes, int n_in,
                              void* d_out, int out_size) {
    const float* brushes = (const float*)d_in[0];   // [32,64,2]
    const float* patches = (const float*)d_in[1];   // [32,64,3,16,16]
    float* out = (float*)d_out;                     // [32,3,256,256]

    brush_tile_kernel<<<32 * 64, 256>>>(brushes, patches, out);
}

// round 7
// speedup vs baseline: 3.6651x; 3.6651x over previous
#include <cuda_runtime.h>
#include <math.h>

#define IMG    256
#define PSZ    16
#define PAD    8
#define WX     28      // aligned x-window
#define WY     24      // y-window
#define NBR    64
#define CH     3
#define INV2S2 12.5f
#define EPSV   1e-7f
#define PADP   20      // patchT row pitch [c][q][p]
#define PFX    28      // FxT row pitch   [q][wl]
#define PFY    24      // FyT row pitch   [p][hl]
#define PT     28      // tT row pitch    [c][p][wl]
#define NBRUSH 2048

__global__ void zero_out_kernel(float4* __restrict__ out, int n4) {
    const int base = blockIdx.x * 768 + threadIdx.x;
    #pragma unroll
    for (int i = 0; i < 3; i++) {
        const int idx = base + i * 256;
        if (idx < n4) out[idx] = make_float4(0.f, 0.f, 0.f, 0.f);
    }
}

// ---- fused scatter: 2 brushes per CTA, in-kernel table filter build ----
__global__ __launch_bounds__(256, 5) void brush_scatter_kernel(
    const float* __restrict__ brushes,   // [B, N, 2]
    const float* __restrict__ patches,   // [B, N, 3, 16, 16]
    float* __restrict__ out)             // [B, 3, 256, 256]
{
    __shared__ __align__(16) float patchT_s[2][CH * PSZ * PADP];
    __shared__ __align__(16) float FxT_s[2][PSZ * PFX];
    __shared__ __align__(16) float FyT_s[2][PSZ * PFY];
    __shared__ __align__(16) float tT_s[2][CH * PSZ * PT];
    __shared__ float e_s[2][2][8];       // [slot][axis][k]
    __shared__ float rden_s[2][2][16];   // [slot][axis][q] (x incl 1/64)
    __shared__ int   t0_s[2][2];
    __shared__ int   w0_s[2][2];

    const int bn0 = blockIdx.x * 2;
    const int b   = bn0 >> 6;
    const int tid = threadIdx.x;

    // ---- phase A: warp 0 builds exp tables + denoms; warps 2-7 load patches ----
    if (tid < 32) {
        const int slot = tid >> 4;
        const int ax   = (tid >> 3) & 1;
        const int k    = tid & 7;
        const float g  = brushes[(bn0 + slot) * 2 + ax] * (float)IMG;
        const int  fl  = (int)floorf(g);
        const int  t0  = fl - 10;
        const float d  = (float)(t0 + k) - (g - 7.5f);
        e_s[slot][ax][k] = __expf(-d * d * INV2S2);
        if (k == 0) {
            t0_s[slot][ax] = t0;
            w0_s[slot][ax] = (ax == 0) ? ((fl - 11) & ~3) : (fl - 11);
        }
        __syncwarp();
        // denominators: each thread covers q = k and q = k+8
        #pragma unroll
        for (int h = 0; h < 2; h++) {
            const int q = k + h * 8;
            int klo = -PAD - q - t0;            if (klo < 0) klo = 0;
            int khi = (IMG + PAD - 1) - q - t0; if (khi > 7) khi = 7;
            float s = 0.f;
            #pragma unroll
            for (int kk = 0; kk < 8; kk++)
                if (kk >= klo && kk <= khi) s += e_s[slot][ax][kk];
            s += EPSV;
            rden_s[slot][ax][q] = (ax == 0) ? 1.f / (s * (float)NBR) : 1.f / s;
        }
    } else if (tid >= 64) {
        const float* pbase = patches + (size_t)bn0 * (CH * PSZ * PSZ);
        const int t = tid - 64;
        #pragma unroll
        for (int it = 0; it < 8; it++) {
            const int i = t + it * 192;          // 1536 elems total
            const int slot = i >= 768;
            const int r = i - slot * 768;
            const int c = r >> 8;
            const int p = (r >> 4) & 15;
            const int q = r & 15;
            patchT_s[slot][(c * PSZ + q) * PADP + p] = pbase[i];
        }
    }
    __syncthreads();

    // ---- phase B: fill FxT[q][wl] (448/slot) + FyT[p][hl] (384/slot) via lookups ----
    for (int i = tid; i < 2 * 832; i += 256) {
        const int slot = i >= 832;
        const int r    = i - slot * 832;
        if (r < PSZ * PFX) {
            const int q  = r / PFX;
            const int wl = r - q * PFX;
            const int w  = w0_s[slot][0] + wl;
            const int idx = w - q - t0_s[slot][0];
            float val = 0.f;
            if (w >= 0 && w < IMG && (unsigned)idx < 8u)
                val = e_s[slot][0][idx] * rden_s[slot][0][q];
            FxT_s[slot][r] = val;
        } else {
            const int rr = r - PSZ * PFX;
            const int p  = rr / PFY;
            const int hl = rr - p * PFY;
            const int h  = w0_s[slot][1] + hl;
            const int idx = h - p - t0_s[slot][1];
            float val = 0.f;
            if (h >= 0 && h < IMG && (unsigned)idx < 8u)
                val = e_s[slot][1][idx] * rden_s[slot][1][p];
            FyT_s[slot][rr] = val;
        }
    }
    __syncthreads();

    // ---- stage 1: tT[c][p][wl] = sum_q FxT[q][wl] * patchT[c][q][p] ----
    if (tid < 168) {
        const int wlq = tid % 7;
        int u = tid / 7;
        const int pg = u & 3;  u >>= 2;
        const int c  = u % 3;
        const int slot = u / 3;
        const int p0  = pg * 4;
        const int wl0 = wlq * 4;

        float acc[4][4] = {};
        #pragma unroll
        for (int q = 0; q < PSZ; q++) {
            const float4 fx = *(const float4*)&FxT_s[slot][q * PFX + wl0];
            const float4 pv = *(const float4*)&patchT_s[slot][(c * PSZ + q) * PADP + p0];
            const float fxa[4] = {fx.x, fx.y, fx.z, fx.w};
            const float pva[4] = {pv.x, pv.y, pv.z, pv.w};
            #pragma unroll
            for (int i = 0; i < 4; i++)
                #pragma unroll
                for (int pp = 0; pp < 4; pp++)
                    acc[i][pp] = fmaf(fxa[i], pva[pp], acc[i][pp]);
        }
        #pragma unroll
        for (int pp = 0; pp < 4; pp++) {
            float4 o = make_float4(acc[0][pp], acc[1][pp], acc[2][pp], acc[3][pp]);
            *(float4*)&tT_s[slot][(c * PSZ + p0 + pp) * PT + wl0] = o;
        }
    }
    __syncthreads();

    // ---- stage 2: 4x4 output blocks, vectorized global reduction ----
    if (tid < 252) {
        const int wlq = tid % 7;
        int u = tid / 7;
        const int hlg = u % 6;  u /= 6;
        const int c   = u % 3;
        const int slot = u / 3;
        const int wl0 = wlq * 4;
        const int hl0 = hlg * 4;

        float acc[4][4] = {};
        #pragma unroll
        for (int p = 0; p < PSZ; p++) {
            const float4 tv = *(const float4*)&tT_s[slot][(c * PSZ + p) * PT + wl0];
            const float4 fy = *(const float4*)&FyT_s[slot][p * PFY + hl0];
            const float fya[4] = {fy.x, fy.y, fy.z, fy.w};
            const float tva[4] = {tv.x, tv.y, tv.z, tv.w};
            #pragma unroll
            for (int i = 0; i < 4; i++)
                #pragma unroll
                for (int k = 0; k < 4; k++)
                    acc[i][k] = fmaf(fya[i], tva[k], acc[i][k]);
        }

        const int wb = w0_s[slot][0] + wl0;
        const int hb = w0_s[slot][1] + hl0;
        float* base = out + ((size_t)b * CH + c) * (IMG * IMG);
        const bool wok = (wb >= 0) && (wb + 3 < IMG);
        #pragma unroll
        for (int i = 0; i < 4; i++) {
            const int h = hb + i;
            if (h < 0 || h >= IMG) continue;
            float* row = base + (size_t)h * IMG;
            if (wok) {
                asm volatile("red.global.add.v4.f32 [%0], {%1, %2, %3, %4};"
                             :: "l"(row + wb), "f"(acc[i][0]), "f"(acc[i][1]),
                                "f"(acc[i][2]), "f"(acc[i][3])
                             : "memory");
            } else {
                #pragma unroll
                for (int k = 0; k < 4; k++) {
                    const int w = wb + k;
                    if (w >= 0 && w < IMG) atomicAdd(row + w, acc[i][k]);
                }
            }
        }
    }
}

extern "C" void kernel_launch(void* const* d_in, const int* in_sizes, int n_in,
                              void* d_out, int out_size) {
    const float* brushes = (const float*)d_in[0];   // [32,64,2]
    const float* patches = (const float*)d_in[1];   // [32,64,3,16,16]
    float* out = (float*)d_out;                     // [32,3,256,256]

    const int n4 = out_size / 4;
    zero_out_kernel<<<(n4 + 767) / 768, 256>>>((float4*)out, n4);
    brush_scatter_kernel<<<NBRUSH / 2, 256>>>(brushes, patches, out);
}

// round 8
// speedup vs baseline: 3.6707x; 1.0015x over previous
#include <cuda_runtime.h>
#include <math.h>

#define IMG    256
#define PSZ    16
#define PAD    8
#define NBR    64
#define CH     3
#define INV2S2 12.5f
#define EPSV   1e-7f
#define PADP   20      // patchT row pitch [c][q][p]
#define PFX    28      // FxT row pitch   [q][wl]
#define PFY    24      // FyT row pitch   [p][hl]
#define PT     28      // tT row pitch    [c][p][wl]
#define NBRUSH 2048
#define SLOTS  4

// dynamic smem layout (floats)
#define SZ_PATCH (CH * PSZ * PADP)   // 960
#define SZ_FX    (PSZ * PFX)         // 448
#define SZ_FY    (PSZ * PFY)         // 384
#define SZ_TT    (CH * PSZ * PT)     // 1344
#define OFF_FX   (SLOTS * SZ_PATCH)             // 3840
#define OFF_FY   (OFF_FX + SLOTS * SZ_FX)       // 5632
#define OFF_TT   (OFF_FY + SLOTS * SZ_FY)       // 7168
#define DYN_FLOATS (OFF_TT + SLOTS * SZ_TT)     // 12544 -> 50176 B

// ---- fused scatter: 4 brushes per CTA, in-kernel table filter build ----
__global__ __launch_bounds__(256) void brush_scatter_kernel(
    const float* __restrict__ brushes,   // [B, N, 2]
    const float* __restrict__ patches,   // [B, N, 3, 16, 16]
    float* __restrict__ out)             // [B, 3, 256, 256]
{
    extern __shared__ __align__(16) float dyn_s[];
    float* patchT_s = dyn_s;                 // [slot][960]
    float* FxT_s    = dyn_s + OFF_FX;        // [slot][448]
    float* FyT_s    = dyn_s + OFF_FY;        // [slot][384]
    float* tT_s     = dyn_s + OFF_TT;        // [slot][1344]

    __shared__ float e_s[SLOTS][2][8];       // [slot][axis][k]
    __shared__ float rden_s[SLOTS][2][16];   // [slot][axis][q] (x incl 1/64)
    __shared__ int   t0_s[SLOTS][2];
    __shared__ int   w0_s[SLOTS][2];

    const int bn0 = blockIdx.x * SLOTS;
    const int b   = bn0 >> 6;
    const int tid = threadIdx.x;

    // ---- phase A: warps 0-1 build exp tables + denoms; warps 2-7 load patches ----
    if (tid < 64) {
        const int slot = tid >> 4;
        const int ax   = (tid >> 3) & 1;
        const int k    = tid & 7;
        const float g  = brushes[(bn0 + slot) * 2 + ax] * (float)IMG;
        const int  fl  = (int)floorf(g);
        const int  t0  = fl - 10;
        const float d  = (float)(t0 + k) - (g - 7.5f);
        e_s[slot][ax][k] = __expf(-d * d * INV2S2);
        if (k == 0) {
            t0_s[slot][ax] = t0;
            w0_s[slot][ax] = (ax == 0) ? ((fl - 11) & ~3) : (fl - 11);
        }
        __syncwarp();
        // denominators: each thread covers q = k and q = k+8
        #pragma unroll
        for (int h = 0; h < 2; h++) {
            const int q = k + h * 8;
            int klo = -PAD - q - t0;            if (klo < 0) klo = 0;
            int khi = (IMG + PAD - 1) - q - t0; if (khi > 7) khi = 7;
            float s = 0.f;
            #pragma unroll
            for (int kk = 0; kk < 8; kk++)
                if (kk >= klo && kk <= khi) s += e_s[slot][ax][kk];
            s += EPSV;
            rden_s[slot][ax][q] = (ax == 0) ? 1.f / (s * (float)NBR) : 1.f / s;
        }
    } else {
        const float* pbase = patches + (size_t)bn0 * (CH * PSZ * PSZ);
        const int t = tid - 64;
        #pragma unroll
        for (int it = 0; it < 16; it++) {
            const int i = t + it * 192;          // 3072 elems total
            const int slot = i / 768;
            const int r = i - slot * 768;
            const int c = r >> 8;
            const int p = (r >> 4) & 15;
            const int q = r & 15;
            patchT_s[slot * SZ_PATCH + (c * PSZ + q) * PADP + p] = pbase[i];
        }
    }
    __syncthreads();

    // ---- phase B: fill FxT[q][wl] + FyT[p][hl] via lookups (4*832 entries) ----
    #pragma unroll
    for (int it = 0; it < 13; it++) {
        const int i = tid + it * 256;
        if (i >= SLOTS * 832) break;
        const int slot = i / 832;
        const int r    = i - slot * 832;
        if (r < PSZ * PFX) {
            const int q  = r / PFX;
            const int wl = r - q * PFX;
            const int w  = w0_s[slot][0] + wl;
            const int idx = w - q - t0_s[slot][0];
            float val = 0.f;
            if (w >= 0 && w < IMG && (unsigned)idx < 8u)
                val = e_s[slot][0][idx] * rden_s[slot][0][q];
            FxT_s[slot * SZ_FX + r] = val;
        } else {
            const int rr = r - PSZ * PFX;
            const int p  = rr / PFY;
            const int hl = rr - p * PFY;
            const int h  = w0_s[slot][1] + hl;
            const int idx = h - p - t0_s[slot][1];
            float val = 0.f;
            if (h >= 0 && h < IMG && (unsigned)idx < 8u)
                val = e_s[slot][1][idx] * rden_s[slot][1][p];
            FyT_s[slot * SZ_FY + rr] = val;
        }
    }
    __syncthreads();

    // ---- stage 1: tT[c][p][wl] = sum_q FxT[q][wl] * patchT[c][q][p] ----
    // tasks: SLOTS * 3 * 4 * 7 = 336
    for (int t = tid; t < SLOTS * 84; t += 256) {
        const int wlq = t % 7;
        int u = t / 7;
        const int pg = u & 3;  u >>= 2;
        const int c  = u % 3;
        const int slot = u / 3;
        const int p0  = pg * 4;
        const int wl0 = wlq * 4;
        const float* fxb = FxT_s + slot * SZ_FX;
        const float* ptb = patchT_s + slot * SZ_PATCH;

        float acc[4][4] = {};
        #pragma unroll
        for (int q = 0; q < PSZ; q++) {
            const float4 fx = *(const float4*)&fxb[q * PFX + wl0];
            const float4 pv = *(const float4*)&ptb[(c * PSZ + q) * PADP + p0];
            const float fxa[4] = {fx.x, fx.y, fx.z, fx.w};
            const float pva[4] = {pv.x, pv.y, pv.z, pv.w};
            #pragma unroll
            for (int i = 0; i < 4; i++)
                #pragma unroll
                for (int pp = 0; pp < 4; pp++)
                    acc[i][pp] = fmaf(fxa[i], pva[pp], acc[i][pp]);
        }
        float* ttb = tT_s + slot * SZ_TT;
        #pragma unroll
        for (int pp = 0; pp < 4; pp++) {
            float4 o = make_float4(acc[0][pp], acc[1][pp], acc[2][pp], acc[3][pp]);
            *(float4*)&ttb[(c * PSZ + p0 + pp) * PT + wl0] = o;
        }
    }
    __syncthreads();

    // ---- stage 2: 4x4 output blocks, vectorized global reduction ----
    // tasks: SLOTS * 3 * 6 * 7 = 504
    for (int t = tid; t < SLOTS * 126; t += 256) {
        const int wlq = t % 7;
        int u = t / 7;
        const int hlg = u % 6;  u /= 6;
        const int c   = u % 3;
        const int slot = u / 3;
        const int wl0 = wlq * 4;
        const int hl0 = hlg * 4;
        const float* ttb = tT_s + slot * SZ_TT;
        const float* fyb = FyT_s + slot * SZ_FY;

        float acc[4][4] = {};
        #pragma unroll
        for (int p = 0; p < PSZ; p++) {
            const float4 tv = *(const float4*)&ttb[(c * PSZ + p) * PT + wl0];
            const float4 fy = *(const float4*)&fyb[p * PFY + hl0];
            const float fya[4] = {fy.x, fy.y, fy.z, fy.w};
            const float tva[4] = {tv.x, tv.y, tv.z, tv.w};
            #pragma unroll
            for (int i = 0; i < 4; i++)
                #pragma unroll
                for (int k = 0; k < 4; k++)
                    acc[i][k] = fmaf(fya[i], tva[k], acc[i][k]);
        }

        const int wb = w0_s[slot][0] + wl0;
        const int hb = w0_s[slot][1] + hl0;
        float* base = out + ((size_t)b * CH + c) * (IMG * IMG);
        const bool wok = (wb >= 0) && (wb + 3 < IMG);
        #pragma unroll
        for (int i = 0; i < 4; i++) {
            const int h = hb + i;
            if (h < 0 || h >= IMG) continue;
            float* row = base + (size_t)h * IMG;
            if (wok) {
                asm volatile("red.global.add.v4.f32 [%0], {%1, %2, %3, %4};"
                             :: "l"(row + wb), "f"(acc[i][0]), "f"(acc[i][1]),
                                "f"(acc[i][2]), "f"(acc[i][3])
                             : "memory");
            } else {
                #pragma unroll
                for (int k = 0; k < 4; k++) {
                    const int w = wb + k;
                    if (w >= 0 && w < IMG) atomicAdd(row + w, acc[i][k]);
                }
            }
        }
    }
}

extern "C" void kernel_launch(void* const* d_in, const int* in_sizes, int n_in,
                              void* d_out, int out_size) {
    const float* brushes = (const float*)d_in[0];   // [32,64,2]
    const float* patches = (const float*)d_in[1];   // [32,64,3,16,16]
    float* out = (float*)d_out;                     // [32,3,256,256]

    static bool attr_set = false;
    if (!attr_set) {
        cudaFuncSetAttribute(brush_scatter_kernel,
                             cudaFuncAttributeMaxDynamicSharedMemorySize,
                             DYN_FLOATS * (int)sizeof(float));
        attr_set = true;
    }

    cudaMemsetAsync(out, 0, (size_t)out_size * sizeof(float), 0);
    brush_scatter_kernel<<<NBRUSH / SLOTS, 256, DYN_FLOATS * sizeof(float)>>>(
        brushes, patches, out);
}